// round 13
// baseline (speedup 1.0000x reference)
#include <cuda_runtime.h>
#include <cuda_bf16.h>
#include <math.h>
#include <stdint.h>

// ---------------------------------------------------------------------------
// Problem constants
// ---------------------------------------------------------------------------
#define NW 1000
#define ND 100
#define NF 100
#define TIw 512
#define HDw 128

// Output layout (concatenated f32)
#define OFF_LAM   0
#define OFF_ZMAT  100
#define OFF_BETA  1000100
#define OFF_GAMMA 1001100
#define OFF_ETA   1001200
#define OFF_ZEV   1001300
#define OFF_H     101001300

#define KMAX 160

// ---------------------------------------------------------------------------
// Device scratch
// ---------------------------------------------------------------------------
__device__ __align__(16) float g_T1[NW * NF];
__device__ __align__(16) float g_T2[NW * NF];
__device__ __align__(16) float g_heli[NW * NF];
__device__ float g_y[NW];
__device__ float g_wp[NF];
__device__ int   g_kci[ND];

#define CSR_CAP 96
__device__ int   g_ccnt[NW];
__device__ int   g_ccol[NW * CSR_CAP];
__device__ float g_cval[NW * CSR_CAP];

__device__ __forceinline__ float warp_sum(float v) {
#pragma unroll
    for (int o = 16; o; o >>= 1) v += __shfl_xor_sync(0xffffffffu, v, o);
    return v;
}

__device__ __forceinline__ float load_scalar(const void* p) {
    int v = *(const int*)p;
    if (v >= 0 && v <= 1000000) return (float)v;
    return *(const float*)p;
}

// ---------------------------------------------------------------------------
// Streams + events (static init; not during capture)
// ---------------------------------------------------------------------------
struct SideRes {
    cudaStream_t s_side, s_a, s_b;
    cudaEvent_t fork, ev_z, ev_t1, ev3, ev_beta, ev_final;
    SideRes() {
        int lo = 0, hi = 0;
        cudaDeviceGetStreamPriorityRange(&lo, &hi);
        cudaStreamCreateWithPriority(&s_side, cudaStreamNonBlocking, lo);
        cudaStreamCreateWithFlags(&s_a, cudaStreamNonBlocking);
        cudaStreamCreateWithFlags(&s_b, cudaStreamNonBlocking);
        cudaEventCreateWithFlags(&fork, cudaEventDisableTiming);
        cudaEventCreateWithFlags(&ev_z, cudaEventDisableTiming);
        cudaEventCreateWithFlags(&ev_t1, cudaEventDisableTiming);
        cudaEventCreateWithFlags(&ev3, cudaEventDisableTiming);
        cudaEventCreateWithFlags(&ev_beta, cudaEventDisableTiming);
        cudaEventCreateWithFlags(&ev_final, cudaEventDisableTiming);
    }
};
static SideRes g_sr;

// ---------------------------------------------------------------------------
// zev_zero — starts only AFTER the latency-critical chain prefix (ev3).
// 2048 blocks: maximize write BW during its (mostly exclusive) window.
// ---------------------------------------------------------------------------
#define ZA4 (100u * 160u * 210u)
#define ZB4 (100u * 840u * 250u)
#define ZT4 (ZA4 + ZB4)

__global__ void __launch_bounds__(256)
zev_zero(float* __restrict__ zev) {
    float4 z = {0.f, 0.f, 0.f, 0.f};
    float4* p = (float4*)zev;
    unsigned g = blockIdx.x * blockDim.x + threadIdx.x;
    unsigned stride = gridDim.x * blockDim.x;
    for (; g < ZT4; g += stride) {
        unsigned off4;
        if (g < ZA4) {
            unsigned d = g / 33600u;
            unsigned rem = g - d * 33600u;
            unsigned i = rem / 210u;
            unsigned q = rem - i * 210u;
            off4 = d * 250000u + i * 250u + 40u + q;
        } else {
            unsigned h = g - ZA4;
            unsigned d = h / 210000u;
            unsigned rem = h - d * 210000u;
            unsigned i2 = rem / 250u;
            unsigned q = rem - i2 * 250u;
            off4 = d * 250000u + (160u + i2) * 250u + q;
        }
        p[off4] = z;
    }
}

// ---------------------------------------------------------------------------
// prep_k (verbatim from r12, passed)
// ---------------------------------------------------------------------------
__global__ void prep_k(const float* __restrict__ adj,
                       const float* __restrict__ wm, const float* __restrict__ Wbeta,
                       const void* ep, const void* eps) {
    int t = threadIdx.x, lane = t & 31, wid = t >> 5;
    if (blockIdx.x < 250) {
        int row = blockIdx.x * 4 + wid;
        const float* r = adj + (size_t)row * NW;
        int cnt = 0;
        for (int base = 0; base < NW; base += 32) {
            int c = base + lane;
            float v = (c < NW) ? r[c] : 0.f;
            unsigned m = __ballot_sync(0xffffffffu, v != 0.f);
            while (m) {
                int b = __ffs(m) - 1;
                m &= m - 1;
                float vb = __shfl_sync(0xffffffffu, v, b);
                if (lane == 0 && cnt < CSR_CAP) {
                    g_ccol[row * CSR_CAP + cnt] = base + b;
                    g_cval[row * CSR_CAP + cnt] = vb;
                }
                ++cnt;
            }
        }
        if (lane == 0) g_ccnt[row] = min(cnt, CSR_CAP);
    } else if (t < NF) {
        float e1 = load_scalar(ep), e2 = load_scalar(eps);
        int j = (int)rintf((e1 / e2) * 0.3f * (float)NF);
        float wi = wm[t];
        int rank = 0;
        for (int l = 0; l < NF; ++l) {
            float wl = wm[l];
            if (wl < wi || (wl == wi && l < t)) ++rank;
        }
        g_wp[t] = (rank >= j) ? Wbeta[t] : 0.f;
    }
}

// ---------------------------------------------------------------------------
// gemm_k (verbatim from r12): T1 = bows @ W_g1
// ---------------------------------------------------------------------------
__global__ void __launch_bounds__(128)
gemm_k(const float* __restrict__ A, const float* __restrict__ B,
       const float* __restrict__ bias, float* __restrict__ C, int flags) {
    __shared__ __align__(16) float sB[NF * NF];
    __shared__ __align__(16) float sA[8 * NF];
    __shared__ float sbias[NF];
    int t = threadIdx.x, lane = t & 31, w = t >> 5;
    int r0 = blockIdx.x * 8;

    for (int i = t; i < NF * NF / 4; i += 128)
        ((float4*)sB)[i] = ((const float4*)B)[i];
    for (int i = t; i < 8 * NF / 4; i += 128)
        ((float4*)sA)[i] = ((const float4*)(A + (size_t)r0 * NF))[i];
    if (t < NF) sbias[t] = bias ? bias[t] : 0.f;
    __syncthreads();

    float acc[2][4] = {};
#pragma unroll 4
    for (int k = 0; k < NF; ++k) {
        float b0 = sB[k * NF + lane];
        float b1 = sB[k * NF + lane + 32];
        float b2 = sB[k * NF + lane + 64];
        float b3 = (lane < 4) ? sB[k * NF + lane + 96] : 0.f;
#pragma unroll
        for (int rr = 0; rr < 2; ++rr) {
            float a = sA[(w * 2 + rr) * NF + k];
            acc[rr][0] = fmaf(a, b0, acc[rr][0]);
            acc[rr][1] = fmaf(a, b1, acc[rr][1]);
            acc[rr][2] = fmaf(a, b2, acc[rr][2]);
            acc[rr][3] = fmaf(a, b3, acc[rr][3]);
        }
    }
    float bb0 = sbias[lane], bb1 = sbias[lane + 32], bb2 = sbias[lane + 64];
    float bb3 = (lane < 4) ? sbias[lane + 96] : 0.f;
#pragma unroll
    for (int rr = 0; rr < 2; ++rr) {
        acc[rr][0] += bb0; acc[rr][1] += bb1; acc[rr][2] += bb2; acc[rr][3] += bb3;
        if (flags & 1) {
            acc[rr][0] = fmaxf(acc[rr][0], 0.f);
            acc[rr][1] = fmaxf(acc[rr][1], 0.f);
            acc[rr][2] = fmaxf(acc[rr][2], 0.f);
            acc[rr][3] = fmaxf(acc[rr][3], 0.f);
        }
        float* Cr = C + (size_t)(r0 + w * 2 + rr) * NF;
        Cr[lane] = acc[rr][0];
        Cr[lane + 32] = acc[rr][1];
        Cr[lane + 64] = acc[rr][2];
        if (lane < 4) Cr[lane + 96] = acc[rr][3];
    }
}

// ---------------------------------------------------------------------------
// rowfuse1 (verbatim from r12)
// ---------------------------------------------------------------------------
__global__ void __launch_bounds__(128)
rowfuse1(const float* __restrict__ T1, const float* __restrict__ Wg2,
         float* __restrict__ T2) {
    __shared__ int   scol[CSR_CAP];
    __shared__ float sval[CSR_CAP];
    __shared__ float sH1[NF];
    int r = blockIdx.x, t = threadIdx.x;
    int nnz = g_ccnt[r];
    if (t < nnz) {
        scol[t] = g_ccol[r * CSR_CAP + t];
        sval[t] = g_cval[r * CSR_CAP + t];
    }
    __syncthreads();
    if (t < NF) {
        float h = 0.f;
#pragma unroll 4
        for (int q = 0; q < nnz; ++q)
            h = fmaf(sval[q], T1[(size_t)scol[q] * NF + t], h);
        sH1[t] = fmaxf(h, 0.f);
    }
    __syncthreads();
    if (t < NF) {
        float acc = 0.f;
#pragma unroll 4
        for (int k = 0; k < NF; ++k)
            acc = fmaf(sH1[k], Wg2[(size_t)k * NF + t], acc);
        T2[(size_t)r * NF + t] = acc;
    }
}

// ---------------------------------------------------------------------------
// rowfuse2 (verbatim from r12)
// ---------------------------------------------------------------------------
__global__ void __launch_bounds__(128)
rowfuse2(const float* __restrict__ T2,
         const float* __restrict__ Wh1, const float* __restrict__ bh1,
         const float* __restrict__ Wh2, const float* __restrict__ bh2,
         float* __restrict__ oH, float* __restrict__ heli) {
    __shared__ int   scol[CSR_CAP];
    __shared__ float sval[CSR_CAP];
    __shared__ float sH[NF];
    __shared__ float sE[NF];
    __shared__ float red[128];
    int r = blockIdx.x, t = threadIdx.x;
    int nnz = g_ccnt[r];
    if (t < nnz) {
        scol[t] = g_ccol[r * CSR_CAP + t];
        sval[t] = g_cval[r * CSR_CAP + t];
    }
    __syncthreads();
    if (t < NF) {
        float h = 0.f;
#pragma unroll 4
        for (int q = 0; q < nnz; ++q)
            h = fmaf(sval[q], T2[(size_t)scol[q] * NF + t], h);
        sH[t] = h;
        oH[(size_t)r * NF + t] = h;
    }
    __syncthreads();
    red[t] = (t < NF) ? sH[t] * g_wp[t] : 0.f;
    __syncthreads();
    for (int s = 64; s; s >>= 1) { if (t < s) red[t] += red[t + s]; __syncthreads(); }
    if (t == 0) g_y[r] = red[0];
    if (t < NF) {
        float e = bh1[t];
#pragma unroll 4
        for (int k = 0; k < NF; ++k)
            e = fmaf(sH[k], Wh1[(size_t)k * NF + t], e);
        sE[t] = fmaxf(e, 0.f);
    }
    __syncthreads();
    float hh = 0.f;
    if (t < NF) {
        hh = bh2[t];
#pragma unroll 4
        for (int k = 0; k < NF; ++k)
            hh = fmaf(sE[k], Wh2[(size_t)k * NF + t], hh);
        hh = fmaxf(hh, 0.f);
    }
    red[t] = (t < NF) ? hh * hh : 0.f;
    __syncthreads();
    for (int s = 64; s; s >>= 1) { if (t < s) red[t] += red[t + s]; __syncthreads(); }
    float inv = 1.f / fmaxf(sqrtf(red[0]), 1e-12f);
    if (t < NF) heli[(size_t)r * NF + t] = hh * inv;
}

// ---------------------------------------------------------------------------
// beta_norm (verbatim)
// ---------------------------------------------------------------------------
__global__ void __launch_bounds__(1024)
beta_norm(float* __restrict__ oBeta) {
    __shared__ float red[1024];
    int t = threadIdx.x;
    float y = (t < NW) ? g_y[t] : 0.f;
    red[t] = y * y;
    __syncthreads();
    for (int s = 512; s; s >>= 1) {
        if (t < s) red[t] += red[t + s];
        __syncthreads();
    }
    float inv = 1.f / fmaxf(sqrtf(red[0]), 1e-12f);
    if (t < NW) oBeta[t] = y * inv;
}

// ---------------------------------------------------------------------------
// gemm_nt_relu (round-2 VERBATIM — protected)
// ---------------------------------------------------------------------------
__global__ void gemm_nt_relu(const float* __restrict__ A, float* __restrict__ C,
                             int M, int K) {
    __shared__ float sA[64][21];
    __shared__ float sB[64][21];
    int tx = threadIdx.x, ty = threadIdx.y;
    int tid = ty * 16 + tx;
    int ib = blockIdx.y * 64, jb = blockIdx.x * 64;
    float acc[4][4] = {};
    for (int k0 = 0; k0 < K; k0 += 20) {
        for (int l = tid; l < 64 * 20; l += 256) {
            int r = l / 20, c = l - r * 20;
            int kk = k0 + c;
            sA[r][c] = (ib + r < M && kk < K) ? A[(size_t)(ib + r) * K + kk] : 0.f;
            sB[r][c] = (jb + r < M && kk < K) ? A[(size_t)(jb + r) * K + kk] : 0.f;
        }
        __syncthreads();
#pragma unroll
        for (int kk = 0; kk < 20; ++kk) {
            float a[4], b[4];
#pragma unroll
            for (int r = 0; r < 4; ++r) a[r] = sA[ty * 4 + r][kk];
#pragma unroll
            for (int c = 0; c < 4; ++c) b[c] = sB[tx * 4 + c][kk];
#pragma unroll
            for (int r = 0; r < 4; ++r)
#pragma unroll
                for (int c = 0; c < 4; ++c) acc[r][c] = fmaf(a[r], b[c], acc[r][c]);
        }
        __syncthreads();
    }
#pragma unroll
    for (int r = 0; r < 4; ++r) {
        int i = ib + ty * 4 + r;
        if (i >= M) continue;
#pragma unroll
        for (int c = 0; c < 4; ++c) {
            int j = jb + tx * 4 + c;
            if (j >= M) continue;
            C[(size_t)i * M + j] = fmaxf(acc[r][c], 0.f);
        }
    }
}

// ---------------------------------------------------------------------------
// doc_k (verbatim)
// ---------------------------------------------------------------------------
__global__ void __launch_bounds__(512)
doc_k(const float* __restrict__ masks, const float* __restrict__ H,
      const float* __restrict__ heli, const float* __restrict__ beta_,
      const float* __restrict__ W_mu2, const float* __restrict__ b_mu2,
      const float* __restrict__ W_eta2, const float* __restrict__ b_eta2,
      const float* __restrict__ W_gm2, const float* __restrict__ b_gm2,
      const float* __restrict__ img, const float* __restrict__ W_m1,
      const float* __restrict__ b_m1, const float* __restrict__ W_m2,
      const float* __restrict__ b_m2,
      float* __restrict__ oLam, float* __restrict__ oEta,
      float* __restrict__ oGamma) {
    __shared__ int   cols[KMAX];
    __shared__ float red[512];
    __shared__ float hp[128];
    __shared__ float simg[TIw];
    __shared__ float sres[8];
    __shared__ int s_cnt;

    int d = blockIdx.x, t = threadIdx.x, lane = t & 31, wid = t >> 5;

    if (wid == 0) {
        const float* mrow = masks + (size_t)d * NW;
        int cnt = 0;
        for (int base = 0; base < NW; base += 32) {
            int c = base + lane;
            float v = (c < NW) ? mrow[c] : 0.f;
            unsigned m = __ballot_sync(0xffffffffu, v != 0.f);
            while (m) {
                int b = __ffs(m) - 1;
                m &= m - 1;
                if (lane == 0 && cnt < KMAX) cols[cnt] = base + b;
                ++cnt;
            }
        }
        if (lane == 0) s_cnt = min(cnt, KMAX);
    }
    __syncthreads();
    int cnt = s_cnt;
    float fk = (float)cnt;

    float sv = 0.f;
    if (t < NF) {
        float hpv = 0.f;
#pragma unroll 4
        for (int q = 0; q < cnt; ++q) {
            int c = cols[q];
            hpv += H[(size_t)c * NF + t];
            sv += heli[(size_t)c * NF + t];
        }
        hp[t] = hpv / fmaxf(fk, 1.f);
    }
    red[t] = (t < NF) ? sv * sv : 0.f;
    __syncthreads();
    for (int s = 256; s; s >>= 1) { if (t < s) red[t] += red[t + s]; __syncthreads(); }
    if (t == 0) sres[0] = red[0];
    __syncthreads();

    red[t] = (t < cnt) ? beta_[cols[t]] : 0.f;
    __syncthreads();
    for (int s = 256; s; s >>= 1) { if (t < s) red[t] += red[t + s]; __syncthreads(); }
    if (t == 0) sres[1] = red[0];
    __syncthreads();

    float hpt = (t < NF) ? hp[t] : 0.f;
    red[t] = (t < NF) ? hpt * W_mu2[t] : 0.f;
    __syncthreads();
    for (int s = 256; s; s >>= 1) { if (t < s) red[t] += red[t + s]; __syncthreads(); }
    if (t == 0) sres[2] = fmaxf(red[0] + b_mu2[0], 0.f);
    __syncthreads();
    red[t] = (t < NF) ? hpt * W_eta2[t] : 0.f;
    __syncthreads();
    for (int s = 256; s; s >>= 1) { if (t < s) red[t] += red[t + s]; __syncthreads(); }
    if (t == 0) sres[3] = fmaxf(red[0] + b_eta2[0], 0.f);
    __syncthreads();
    red[t] = (t < NF) ? hpt * W_gm2[t] : 0.f;
    __syncthreads();
    for (int s = 256; s; s >>= 1) { if (t < s) red[t] += red[t + s]; __syncthreads(); }
    if (t == 0) sres[4] = fmaxf(red[0] + b_gm2[0], 0.f);
    __syncthreads();

    for (int k = t; k < TIw; k += 512) simg[k] = img[(size_t)d * TIw + k];
    __syncthreads();
    float contrib = 0.f;
    if (t < HDw) {
        float h0 = b_m1[t], h1 = 0.f, h2 = 0.f, h3 = 0.f;
#pragma unroll 4
        for (int k = 0; k < TIw; k += 4) {
            h0 = fmaf(simg[k],     W_m1[(size_t)k * HDw + t],       h0);
            h1 = fmaf(simg[k + 1], W_m1[(size_t)(k + 1) * HDw + t], h1);
            h2 = fmaf(simg[k + 2], W_m1[(size_t)(k + 2) * HDw + t], h2);
            h3 = fmaf(simg[k + 3], W_m1[(size_t)(k + 3) * HDw + t], h3);
        }
        contrib = fmaxf((h0 + h1) + (h2 + h3), 0.f) * W_m2[t];
    }
    red[t] = contrib;
    __syncthreads();
    for (int s = 256; s; s >>= 1) { if (t < s) red[t] += red[t + s]; __syncthreads(); }

    if (t == 0) {
        float li = red[0] + b_m2[0];
        float Z = fmaxf(0.5f * (sres[0] - fk), 0.f);
        float inner = sres[2] + sres[1] + sres[3] * expf(-sres[4] * Z);
        float lt = 1.f / (1.f + expf(-inner));
        oLam[d] = 1.f / (1.f + expf(-(lt + li)));
        oEta[d] = sres[3];
        oGamma[d] = sres[4];
        g_kci[d] = cnt;
    }
}

// ---------------------------------------------------------------------------
// zev_patch (verbatim)
// ---------------------------------------------------------------------------
__global__ void __launch_bounds__(256)
zev_patch(const float* __restrict__ oZ, float* __restrict__ zev) {
    unsigned g = blockIdx.x * 256u + threadIdx.x;
    if (g >= 640000u) return;
    unsigned d = g / 6400u;
    unsigned rem = g - d * 6400u;
    unsigned i = rem / 40u;
    unsigned q = rem - i * 40u;
    unsigned j0 = q << 2;
    int kd = g_kci[d];
    float4 v = {0.f, 0.f, 0.f, 0.f};
    if ((int)i < kd) {
        const float* zr = oZ + (size_t)i * NW + j0;
        float* vv = (float*)&v;
#pragma unroll
        for (int c = 0; c < 4; ++c) {
            int j = (int)j0 + c;
            if (j < kd && j != (int)i) {
                float tt = 2.f - 2.f * zr[c];
                vv[c] = expf(-tt * tt);
            }
        }
    }
    *(float4*)(zev + (size_t)d * NW * NW + (size_t)i * NW + j0) = v;
}

// ---------------------------------------------------------------------------
// Host launch — contention-aware schedule:
//   phase 1 (uncontended): prep ∥ T1 -> rowfuse1 -> rowfuse2
//   phase 2 (overlapped):  zev_zero ∥ {beta, zgemm, doc}
//   phase 3: patch
// ---------------------------------------------------------------------------
extern "C" void kernel_launch(void* const* d_in, const int* in_sizes, int n_in,
                              void* d_out, int out_size) {
    (void)in_sizes; (void)n_in; (void)out_size;
    const void*  epoch  = d_in[0];
    const void*  epochs = d_in[1];
    const float* adj    = (const float*)d_in[2];
    const float* masks  = (const float*)d_in[3];
    const float* bows   = (const float*)d_in[4];
    const float* img    = (const float*)d_in[5];
    const float* W_g1   = (const float*)d_in[6];
    const float* W_g2   = (const float*)d_in[7];
    const float* W_h1   = (const float*)d_in[8];
    const float* b_h1   = (const float*)d_in[9];
    const float* W_h2   = (const float*)d_in[10];
    const float* b_h2   = (const float*)d_in[11];
    const float* W_mu2  = (const float*)d_in[12];
    const float* b_mu2  = (const float*)d_in[13];
    const float* W_eta2 = (const float*)d_in[14];
    const float* b_eta2 = (const float*)d_in[15];
    const float* W_gm2  = (const float*)d_in[16];
    const float* b_gm2  = (const float*)d_in[17];
    const float* w_m    = (const float*)d_in[18];
    const float* W_beta = (const float*)d_in[19];
    const float* W_m1   = (const float*)d_in[20];
    const float* b_m1   = (const float*)d_in[21];
    const float* W_m2   = (const float*)d_in[22];
    const float* b_m2   = (const float*)d_in[23];

    float* out = (float*)d_out;
    float* oLam   = out + OFF_LAM;
    float* oZ     = out + OFF_ZMAT;
    float* oBeta  = out + OFF_BETA;
    float* oGamma = out + OFF_GAMMA;
    float* oEta   = out + OFF_ETA;
    float* oZev   = out + OFF_ZEV;
    float* oH     = out + OFF_H;

    float *pT1, *pT2, *pHeli;
    cudaGetSymbolAddress((void**)&pT1, g_T1);
    cudaGetSymbolAddress((void**)&pT2, g_T2);
    cudaGetSymbolAddress((void**)&pHeli, g_heli);

    // fork from capture stream
    cudaEventRecord(g_sr.fork, 0);

    // ---- phase 1 (uncontended latency-critical prefix) ----
    // s_b: T1 = bows @ W_g1
    cudaStreamWaitEvent(g_sr.s_b, g_sr.fork, 0);
    gemm_k<<<125, 128, 0, g_sr.s_b>>>(bows, W_g1, nullptr, pT1, 0);
    cudaEventRecord(g_sr.ev_t1, g_sr.s_b);

    // s_a: prep
    cudaStreamWaitEvent(g_sr.s_a, g_sr.fork, 0);
    prep_k<<<251, 128, 0, g_sr.s_a>>>(adj, w_m, W_beta, epoch, epochs);

    cudaStreamWaitEvent(g_sr.s_a, g_sr.ev_t1, 0);
    rowfuse1<<<NW, 128, 0, g_sr.s_a>>>(pT1, W_g2, pT2);
    rowfuse2<<<NW, 128, 0, g_sr.s_a>>>(pT2, W_h1, b_h1, W_h2, b_h2, oH, pHeli);
    cudaEventRecord(g_sr.ev3, g_sr.s_a);

    // ---- phase 2: big fill starts ONLY now, overlapping the short tail ----
    cudaStreamWaitEvent(g_sr.s_side, g_sr.ev3, 0);
    zev_zero<<<2048, 256, 0, g_sr.s_side>>>(oZev);
    cudaEventRecord(g_sr.ev_z, g_sr.s_side);

    // tail on s_b: beta_norm (needs g_y from rowfuse2)
    cudaStreamWaitEvent(g_sr.s_b, g_sr.ev3, 0);
    beta_norm<<<1, 1024, 0, g_sr.s_b>>>(oBeta);
    cudaEventRecord(g_sr.ev_beta, g_sr.s_b);

    // tail on s_a: Z_ GEMM
    {
        dim3 grid((NW + 63) / 64, (NW + 63) / 64);
        dim3 block(16, 16);
        gemm_nt_relu<<<grid, block, 0, g_sr.s_a>>>(pHeli, oZ, NW, NF);
    }

    // doc (needs beta + heli + H)
    cudaStreamWaitEvent(g_sr.s_a, g_sr.ev_beta, 0);
    doc_k<<<ND, 512, 0, g_sr.s_a>>>(masks, oH, pHeli, oBeta,
                                    W_mu2, b_mu2, W_eta2, b_eta2, W_gm2, b_gm2,
                                    img, W_m1, b_m1, W_m2, b_m2,
                                    oLam, oEta, oGamma);

    // ---- phase 3: patch (needs Z_, kci, zero region) ----
    cudaStreamWaitEvent(g_sr.s_a, g_sr.ev_z, 0);
    zev_patch<<<2500, 256, 0, g_sr.s_a>>>(oZ, oZev);
    cudaEventRecord(g_sr.ev_final, g_sr.s_a);

    // join back to the capture stream
    cudaStreamWaitEvent(0, g_sr.ev_final, 0);
}